// round 2
// baseline (speedup 1.0000x reference)
#include <cuda_runtime.h>
#include <cstdint>
#include <cstddef>

#define NN   100000
#define EE   1600000
#define DIN  165
#define DMID 82
#define DH   128
#define DG   64

// ---------------- scratch (static device globals; no cudaMalloc allowed) ----
__device__ float g_t  [NN * DMID];   // relu(x@W1)
__device__ float g_y1 [NN * DIN];    // boosted features
__device__ float g_agg[NN * DIN];    // SAGE mean aggregate
__device__ float g_x2 [NN * DH];     // SAGE output
__device__ float g_h  [NN * DG];     // GAT projected features
__device__ float g_as [NN];
__device__ float g_ad [NN];
__device__ int   g_cnt [NN];
__device__ int   g_rowptr[NN + 1];
__device__ int   g_cursor[NN];
__device__ int   g_bsum[256];
__device__ int   g_col [EE];

// ---------------- warp reduce helpers ---------------------------------------
__device__ __forceinline__ float wredmax(float v) {
    #pragma unroll
    for (int o = 16; o; o >>= 1) v = fmaxf(v, __shfl_xor_sync(0xffffffffu, v, o));
    return v;
}
__device__ __forceinline__ float wredsum(float v) {
    #pragma unroll
    for (int o = 16; o; o >>= 1) v += __shfl_xor_sync(0xffffffffu, v, o);
    return v;
}

// ---------------- CSR build --------------------------------------------------
__global__ void k_zero_cnt(int n) {
    int i = blockIdx.x * blockDim.x + threadIdx.x;
    if (i < n) g_cnt[i] = 0;
}

// edge_index arrives as int32 (JAX default x64-disabled): row0 = src, row1 = dst
__global__ void k_hist(const int* __restrict__ ei, int e, int n) {
    int i = blockIdx.x * blockDim.x + threadIdx.x;
    if (i < e) {
        int d = ei[e + i];   // dst row
        if ((unsigned)d < (unsigned)n) atomicAdd(&g_cnt[d], 1);
    }
}

// block-local exclusive scan (1024 elems/block), emit block sums
__global__ void k_scan1(int n) {
    __shared__ int sh[1024];
    int t = threadIdx.x;
    int i = blockIdx.x * 1024 + t;
    int v = (i < n) ? g_cnt[i] : 0;
    sh[t] = v;
    __syncthreads();
    #pragma unroll
    for (int off = 1; off < 1024; off <<= 1) {
        int x = (t >= off) ? sh[t - off] : 0;
        __syncthreads();
        sh[t] += x;
        __syncthreads();
    }
    int incl = sh[t];
    if (i < n) g_rowptr[i] = incl - v;   // local exclusive
    if (t == 1023) g_bsum[blockIdx.x] = incl;
}

__global__ void k_scan2(int nb) {
    if (threadIdx.x == 0 && blockIdx.x == 0) {
        int run = 0;
        for (int b = 0; b < nb; b++) { int t = g_bsum[b]; g_bsum[b] = run; run += t; }
    }
}

__global__ void k_scan3(int n, int e) {
    int i = blockIdx.x * blockDim.x + threadIdx.x;
    if (i < n) {
        int v = g_rowptr[i] + g_bsum[i >> 10];
        g_rowptr[i] = v;
        g_cursor[i] = v;
    }
    if (i == 0) g_rowptr[n] = e;
}

__global__ void k_fill(const int* __restrict__ ei, int e, int n) {
    int i = blockIdx.x * blockDim.x + threadIdx.x;
    if (i < e) {
        int d = ei[e + i];
        int s = ei[i];
        if ((unsigned)d < (unsigned)n && (unsigned)s < (unsigned)n) {
            int pos = atomicAdd(&g_cursor[d], 1);
            g_col[pos] = s;
        }
    }
}

// ---------------- tiled SGEMM core (64x64 tile, 4x4 microtile, 256 thr) -----
template<int K, int M>
__device__ __forceinline__ void gemm_tile(
    const float* __restrict__ A, const float* __restrict__ W,
    int n, int rowBase, int colBase, int tid,
    float (*sA)[33], float (*sW)[64], float (&acc)[4][4])
{
    const int tx = tid & 15, ty = tid >> 4;
    for (int k0 = 0; k0 < K; k0 += 32) {
        #pragma unroll
        for (int i = 0; i < 8; i++) {
            int idx = tid + i * 256;
            int r = idx >> 5, kk = idx & 31;
            int row = rowBase + r, k = k0 + kk;
            sA[r][kk] = (row < n && k < K) ? A[(size_t)row * K + k] : 0.0f;
        }
        #pragma unroll
        for (int i = 0; i < 8; i++) {
            int idx = tid + i * 256;
            int kk = idx >> 6, c = idx & 63;
            int k = k0 + kk, col = colBase + c;
            sW[kk][c] = (k < K && col < M) ? W[(size_t)k * M + col] : 0.0f;
        }
        __syncthreads();
        #pragma unroll
        for (int kk = 0; kk < 32; kk++) {
            float4 b = *(const float4*)&sW[kk][tx * 4];
            float a0 = sA[ty * 4 + 0][kk];
            float a1 = sA[ty * 4 + 1][kk];
            float a2 = sA[ty * 4 + 2][kk];
            float a3 = sA[ty * 4 + 3][kk];
            acc[0][0] += a0 * b.x; acc[0][1] += a0 * b.y; acc[0][2] += a0 * b.z; acc[0][3] += a0 * b.w;
            acc[1][0] += a1 * b.x; acc[1][1] += a1 * b.y; acc[1][2] += a1 * b.z; acc[1][3] += a1 * b.w;
            acc[2][0] += a2 * b.x; acc[2][1] += a2 * b.y; acc[2][2] += a2 * b.z; acc[2][3] += a2 * b.w;
            acc[3][0] += a3 * b.x; acc[3][1] += a3 * b.y; acc[3][2] += a3 * b.z; acc[3][3] += a3 * b.w;
        }
        __syncthreads();
    }
}

// FB stage 1: g_t = relu(x @ fb_w1)
__global__ __launch_bounds__(256) void k_fb1(const float* __restrict__ x,
                                             const float* __restrict__ w1, int n)
{
    __shared__ float sA[64][33];
    __shared__ float sW[32][64];
    float acc[4][4] = {};
    int tid = threadIdx.x;
    int rowBase = blockIdx.y * 64, colBase = blockIdx.x * 64;
    gemm_tile<DIN, DMID>(x, w1, n, rowBase, colBase, tid, sA, sW, acc);
    int tx = tid & 15, ty = tid >> 4;
    #pragma unroll
    for (int i = 0; i < 4; i++) {
        int r = rowBase + ty * 4 + i;
        if (r >= n) continue;
        #pragma unroll
        for (int j = 0; j < 4; j++) {
            int c = colBase + tx * 4 + j;
            if (c < DMID) g_t[(size_t)r * DMID + c] = fmaxf(acc[i][j], 0.0f);
        }
    }
}

// FB stage 2: g_y1 = x * sigmoid(2 * (g_t @ fb_w2))
__global__ __launch_bounds__(256) void k_fb2(const float* __restrict__ x,
                                             const float* __restrict__ w2, int n)
{
    __shared__ float sA[64][33];
    __shared__ float sW[32][64];
    float acc[4][4] = {};
    int tid = threadIdx.x;
    int rowBase = blockIdx.y * 64, colBase = blockIdx.x * 64;
    gemm_tile<DMID, DIN>(g_t, w2, n, rowBase, colBase, tid, sA, sW, acc);
    int tx = tid & 15, ty = tid >> 4;
    #pragma unroll
    for (int i = 0; i < 4; i++) {
        int r = rowBase + ty * 4 + i;
        if (r >= n) continue;
        #pragma unroll
        for (int j = 0; j < 4; j++) {
            int c = colBase + tx * 4 + j;
            if (c < DIN) {
                float sig = 1.0f / (1.0f + __expf(-2.0f * acc[i][j]));
                g_y1[(size_t)r * DIN + c] = x[(size_t)r * DIN + c] * sig;
            }
        }
    }
}

// SAGE mean aggregation: warp per dst node, pure gather via CSR
__global__ __launch_bounds__(256) void k_sage_agg(int n)
{
    int w = (blockIdx.x * blockDim.x + threadIdx.x) >> 5;
    int lane = threadIdx.x & 31;
    if (w >= n) return;
    int beg = g_rowptr[w], end = g_rowptr[w + 1];
    float acc[6] = {0.f, 0.f, 0.f, 0.f, 0.f, 0.f};
    int e = beg;
    for (; e + 2 <= end; e += 2) {
        int s0 = g_col[e], s1 = g_col[e + 1];
        const float* p0 = g_y1 + (size_t)s0 * DIN;
        const float* p1 = g_y1 + (size_t)s1 * DIN;
        #pragma unroll
        for (int t = 0; t < 6; t++) {
            int d = lane + 32 * t;
            if (d < DIN) acc[t] += p0[d] + p1[d];
        }
    }
    if (e < end) {
        const float* p0 = g_y1 + (size_t)g_col[e] * DIN;
        #pragma unroll
        for (int t = 0; t < 6; t++) {
            int d = lane + 32 * t;
            if (d < DIN) acc[t] += p0[d];
        }
    }
    float inv = 1.0f / fmaxf((float)(end - beg), 1.0f);
    #pragma unroll
    for (int t = 0; t < 6; t++) {
        int d = lane + 32 * t;
        if (d < DIN) g_agg[(size_t)w * DIN + d] = acc[t] * inv;
    }
}

// SAGE linear: g_x2 = relu(agg @ wl + y1 @ wr + bl)
__global__ __launch_bounds__(256) void k_sage_gemm(const float* __restrict__ wl,
                                                   const float* __restrict__ bl,
                                                   const float* __restrict__ wr, int n)
{
    __shared__ float sA[64][33];
    __shared__ float sW[32][64];
    float acc[4][4] = {};
    int tid = threadIdx.x;
    int rowBase = blockIdx.y * 64, colBase = blockIdx.x * 64;
    gemm_tile<DIN, DH>(g_agg, wl, n, rowBase, colBase, tid, sA, sW, acc);
    gemm_tile<DIN, DH>(g_y1,  wr, n, rowBase, colBase, tid, sA, sW, acc);
    int tx = tid & 15, ty = tid >> 4;
    #pragma unroll
    for (int i = 0; i < 4; i++) {
        int r = rowBase + ty * 4 + i;
        if (r >= n) continue;
        #pragma unroll
        for (int j = 0; j < 4; j++) {
            int c = colBase + tx * 4 + j;
            if (c < DH) g_x2[(size_t)r * DH + c] = fmaxf(acc[i][j] + bl[c], 0.0f);
        }
    }
}

// GAT projection: g_h = g_x2 @ gat_w
__global__ __launch_bounds__(256) void k_gat_h(const float* __restrict__ gw, int n)
{
    __shared__ float sA[64][33];
    __shared__ float sW[32][64];
    float acc[4][4] = {};
    int tid = threadIdx.x;
    int rowBase = blockIdx.y * 64, colBase = blockIdx.x * 64;
    gemm_tile<DH, DG>(g_x2, gw, n, rowBase, colBase, tid, sA, sW, acc);
    int tx = tid & 15, ty = tid >> 4;
    #pragma unroll
    for (int i = 0; i < 4; i++) {
        int r = rowBase + ty * 4 + i;
        if (r >= n) continue;
        #pragma unroll
        for (int j = 0; j < 4; j++) {
            int c = colBase + tx * 4 + j;
            if (c < DG) g_h[(size_t)r * DG + c] = acc[i][j];
        }
    }
}

// attention logits per node: a_s = h@att_src, a_d = h@att_dst (warp per node)
__global__ __launch_bounds__(256) void k_att(const float* __restrict__ att_s,
                                             const float* __restrict__ att_d, int n)
{
    int w = (blockIdx.x * blockDim.x + threadIdx.x) >> 5;
    int lane = threadIdx.x & 31;
    if (w >= n) return;
    const float* hp = g_h + (size_t)w * DG;
    float h0 = hp[lane], h1 = hp[lane + 32];
    float ps = h0 * att_s[lane] + h1 * att_s[lane + 32];
    float pd = h0 * att_d[lane] + h1 * att_d[lane + 32];
    ps = wredsum(ps);
    pd = wredsum(pd);
    if (lane == 0) { g_as[w] = ps; g_ad[w] = pd; }
}

// GAT softmax-aggregate + bias + relu + Cheb(64->1) + sigmoid, fully fused.
// Warp per dst node over its CSR segment; self-loop handled in-register.
__global__ __launch_bounds__(256) void k_gat_agg(const float* __restrict__ gat_b,
                                                 const float* __restrict__ cheb_w,
                                                 const float* __restrict__ cheb_b,
                                                 float* __restrict__ out, int n)
{
    int w = (blockIdx.x * blockDim.x + threadIdx.x) >> 5;
    int lane = threadIdx.x & 31;
    if (w >= n) return;
    int beg = g_rowptr[w], end = g_rowptr[w + 1];
    float ad_i = g_ad[w];
    float es = g_as[w] + ad_i;
    es = es > 0.0f ? es : 0.2f * es;            // self-loop leaky relu
    float m = es;
    // pass 1: max
    for (int base = beg; base < end; base += 32) {
        int j = base + lane;
        float e = -1e30f;
        if (j < end) {
            int s = g_col[j];
            float t = g_as[s] + ad_i;
            e = t > 0.0f ? t : 0.2f * t;
        }
        m = fmaxf(m, e);
    }
    m = wredmax(m);
    // pass 2: exp weights + weighted h sum
    float sl = 0.0f, a0 = 0.0f, a1 = 0.0f;
    for (int base = beg; base < end; base += 32) {
        int j = base + lane;
        int s = 0;
        float wgt = 0.0f;
        if (j < end) {
            s = g_col[j];
            float t = g_as[s] + ad_i;
            t = t > 0.0f ? t : 0.2f * t;
            wgt = __expf(t - m);
        }
        sl += wgt;
        int cnt = min(32, end - base);
        for (int jj = 0; jj < cnt; jj++) {
            float wj = __shfl_sync(0xffffffffu, wgt, jj);
            int   sj = __shfl_sync(0xffffffffu, s, jj);
            const float* hp = g_h + (size_t)sj * DG;
            a0 += wj * hp[lane];
            a1 += wj * hp[lane + 32];
        }
    }
    float ws = __expf(es - m);
    float stot = wredsum(sl) + ws;
    const float* hi = g_h + (size_t)w * DG;
    a0 += ws * hi[lane];
    a1 += ws * hi[lane + 32];
    float r = 1.0f / (stot + 1e-16f);
    float x0 = fmaxf(a0 * r + gat_b[lane], 0.0f);
    float x1 = fmaxf(a1 * r + gat_b[lane + 32], 0.0f);
    float part = x0 * cheb_w[lane] + x1 * cheb_w[lane + 32];
    part = wredsum(part);
    if (lane == 0) out[w] = 1.0f / (1.0f + __expf(-(part + cheb_b[0])));
}

// ---------------- launch -----------------------------------------------------
extern "C" void kernel_launch(void* const* d_in, const int* in_sizes, int n_in,
                              void* d_out, int out_size)
{
    const float* x       = (const float*)d_in[0];
    const int*   ei      = (const int*)d_in[1];       // int32 (JAX x64 disabled)
    const float* fb_w1   = (const float*)d_in[2];
    const float* fb_w2   = (const float*)d_in[3];
    const float* sage_wl = (const float*)d_in[4];
    const float* sage_bl = (const float*)d_in[5];
    const float* sage_wr = (const float*)d_in[6];
    const float* gat_w   = (const float*)d_in[7];
    const float* att_s   = (const float*)d_in[8];
    const float* att_d   = (const float*)d_in[9];
    const float* gat_b   = (const float*)d_in[10];
    const float* cheb_w  = (const float*)d_in[11];
    const float* cheb_b  = (const float*)d_in[12];
    float*       out     = (float*)d_out;

    int n = in_sizes[0] / DIN;
    int e = in_sizes[1] / 2;

    // CSR build (by dst)
    k_zero_cnt<<<(n + 255) / 256, 256>>>(n);
    k_hist<<<(e + 255) / 256, 256>>>(ei, e, n);
    int nb = (n + 1023) / 1024;
    k_scan1<<<nb, 1024>>>(n);
    k_scan2<<<1, 32>>>(nb);
    k_scan3<<<(n + 255) / 256, 256>>>(n, e);
    k_fill<<<(e + 255) / 256, 256>>>(ei, e, n);

    int rowTiles = (n + 63) / 64;
    // FeatureBooster
    { dim3 g(2, rowTiles); k_fb1<<<g, 256>>>(x, fb_w1, n); }
    { dim3 g(3, rowTiles); k_fb2<<<g, 256>>>(x, fb_w2, n); }
    // SAGE
    k_sage_agg<<<(n + 7) / 8, 256>>>(n);
    { dim3 g(2, rowTiles); k_sage_gemm<<<g, 256>>>(sage_wl, sage_bl, sage_wr, n); }
    // GAT
    { dim3 g(1, rowTiles); k_gat_h<<<g, 256>>>(gat_w, n); }
    k_att<<<(n + 7) / 8, 256>>>(att_s, att_d, n);
    k_gat_agg<<<(n + 7) / 8, 256>>>(gat_b, cheb_w, cheb_b, out, n);
}